// round 1
// baseline (speedup 1.0000x reference)
#include <cuda_runtime.h>
#include <math_constants.h>

// Bidirectional Chamfer distance, B=4, N=M=4096, D=3, fp32.
// dist[b,n,m] = |q|^2 + |t|^2 - 2 q.t  (same expansion as reference)
// Strategy: per-(batch,dir) min over targets via shared-mem tiled FMA loop,
// partial mins merged with atomicMin on an order-preserving uint key.

#define BATCH   4
#define NPTS    4096
#define THREADS 256
#define QPT     2                    // queries per thread
#define QBLK    (THREADS * QPT)      // 512 queries per block
#define TT      2048                 // targets per tile (2 tiles)
#define NQBLK   (NPTS / QBLK)        // 8
#define NTTILE  (NPTS / TT)          // 2
#define MINBUF_N (2 * BATCH * NPTS)  // 32768

// scratch: per-(dir,batch,query) running min, as monotone uint key
__device__ unsigned int g_minbuf[MINBUF_N];

// order-preserving float <-> uint key (handles negatives from fp cancellation)
__device__ __forceinline__ unsigned int f2key(float f) {
    unsigned int u = __float_as_uint(f);
    return (u & 0x80000000u) ? ~u : (u | 0x80000000u);
}
__device__ __forceinline__ float key2f(unsigned int k) {
    unsigned int u = (k & 0x80000000u) ? (k & 0x7FFFFFFFu) : ~k;
    return __uint_as_float(u);
}

__global__ void init_minbuf_kernel() {
    int i = blockIdx.x * blockDim.x + threadIdx.x;
    if (i < MINBUF_N) g_minbuf[i] = 0xFFFFFFFFu;  // max key = +inf-ish
}

__global__ __launch_bounds__(THREADS)
void chamfer_min_kernel(const float* __restrict__ src,
                        const float* __restrict__ tgt) {
    __shared__ float4 s_t[TT];

    const int bz  = blockIdx.z;     // 0..7 = b*2 + dir
    const int b   = bz >> 1;
    const int dir = bz & 1;

    const float* __restrict__ qbase = (dir ? tgt : src) + (size_t)b * NPTS * 3;
    const float* __restrict__ tbase = (dir ? src : tgt) + (size_t)b * NPTS * 3;

    // --- load + preprocess target tile into shared: (-2x, -2y, -2z, |t|^2)
    const int t0 = blockIdx.y * TT;
    for (int i = threadIdx.x; i < TT; i += THREADS) {
        float x = tbase[(t0 + i) * 3 + 0];
        float y = tbase[(t0 + i) * 3 + 1];
        float z = tbase[(t0 + i) * 3 + 2];
        s_t[i] = make_float4(-2.0f * x, -2.0f * y, -2.0f * z,
                             fmaf(x, x, fmaf(y, y, z * z)));
    }
    __syncthreads();

    // --- load this thread's queries
    const int q0 = blockIdx.x * QBLK;
    float qx[QPT], qy[QPT], qz[QPT], q2[QPT], mn[QPT];
#pragma unroll
    for (int j = 0; j < QPT; j++) {
        int q = q0 + threadIdx.x + j * THREADS;
        qx[j] = qbase[q * 3 + 0];
        qy[j] = qbase[q * 3 + 1];
        qz[j] = qbase[q * 3 + 2];
        q2[j] = fmaf(qx[j], qx[j], fmaf(qy[j], qy[j], qz[j] * qz[j]));
        mn[j] = CUDART_INF_F;
    }

    // --- main loop: 3 FFMA + 1 FMNMX per (query,target) pair
#pragma unroll 4
    for (int i = 0; i < TT; i++) {
        float4 t = s_t[i];
#pragma unroll
        for (int j = 0; j < QPT; j++) {
            float s = fmaf(t.z, qz[j], t.w);
            s = fmaf(t.y, qy[j], s);
            s = fmaf(t.x, qx[j], s);
            mn[j] = fminf(mn[j], s);
        }
    }

    // --- merge partial mins (add |q|^2 here; constant per query)
    unsigned int* buf = g_minbuf + (size_t)(dir * BATCH + b) * NPTS;
#pragma unroll
    for (int j = 0; j < QPT; j++) {
        int q = q0 + threadIdx.x + j * THREADS;
        atomicMin(&buf[q], f2key(mn[j] + q2[j]));
    }
}

// Single-block deterministic reduction:
// loss = sum(all per-point mins) / (B * N)
__global__ __launch_bounds__(1024)
void chamfer_reduce_kernel(float* __restrict__ out) {
    __shared__ float s_sum[1024];
    float acc = 0.0f;
    for (int i = threadIdx.x; i < MINBUF_N; i += 1024)
        acc += key2f(g_minbuf[i]);
    s_sum[threadIdx.x] = acc;
    __syncthreads();
    for (int stride = 512; stride > 0; stride >>= 1) {
        if (threadIdx.x < stride) s_sum[threadIdx.x] += s_sum[threadIdx.x + stride];
        __syncthreads();
    }
    if (threadIdx.x == 0)
        out[0] = s_sum[0] / (float)(BATCH * NPTS);
}

extern "C" void kernel_launch(void* const* d_in, const int* in_sizes, int n_in,
                              void* d_out, int out_size) {
    const float* src = (const float*)d_in[0];  // (B, N, 3)
    const float* tgt = (const float*)d_in[1];  // (B, M, 3)
    float* out = (float*)d_out;

    init_minbuf_kernel<<<(MINBUF_N + 255) / 256, 256>>>();

    dim3 grid(NQBLK, NTTILE, 2 * BATCH);  // 8 x 2 x 8 = 128 blocks
    chamfer_min_kernel<<<grid, THREADS>>>(src, tgt);

    chamfer_reduce_kernel<<<1, 1024>>>(out);
}

// round 2
// speedup vs baseline: 1.2534x; 1.2534x over previous
#include <cuda_runtime.h>
#include <math_constants.h>

// Bidirectional Chamfer distance, B=4, N=M=4096, D=3, fp32.
// dist = |q|^2 + |t|^2 - 2 q.t ; per-query min via packed f32x2 FMA
// (2 targets per FMA-pipe issue), partial mins per target-tile plain-stored,
// merged + summed in a second kernel. No atomics, no init kernel.

#define BATCH   4
#define NPTS    4096
#define THREADS 256
#define QPT     2                    // queries per thread
#define QBLK    (THREADS * QPT)      // 512 queries per block
#define NQBLK   (NPTS / QBLK)        // 8
#define NTTILE  4                    // target tiles
#define TT      (NPTS / NTTILE)      // 1024 targets per tile
#define TTP     (TT / 2)             // 512 target PAIRS per tile
#define NDIRB   (2 * BATCH)          // 8
#define PART_N  (NTTILE * NDIRB * NPTS)  // 131072 partial mins

// partial[tile][dir*B+b][q]
__device__ float g_partial[PART_N];

__global__ __launch_bounds__(THREADS, 2)
void chamfer_min_kernel(const float* __restrict__ src,
                        const float* __restrict__ tgt) {
    // target pairs, packed for f32x2:
    //   s_xy[p] = (x0,x1, y0,y1)  (x,y pre-scaled by -2)
    //   s_zw[p] = (z0,z1, w0,w1)  (z pre-scaled by -2, w = |t|^2)
    __shared__ float4 s_xy[TTP];
    __shared__ float4 s_zw[TTP];

    const int bz  = blockIdx.z;     // 0..7 = b*2 + dir
    const int b   = bz >> 1;
    const int dir = bz & 1;

    const float* __restrict__ qbase = (dir ? tgt : src) + (size_t)b * NPTS * 3;
    const float* __restrict__ tbase = (dir ? src : tgt) + (size_t)b * NPTS * 3;

    // --- preprocess target tile into paired layout
    const int t0 = blockIdx.y * TT;
    for (int p = threadIdx.x; p < TTP; p += THREADS) {
        const float* tp = tbase + (size_t)(t0 + 2 * p) * 3;
        float x0 = tp[0], y0 = tp[1], z0 = tp[2];
        float x1 = tp[3], y1 = tp[4], z1 = tp[5];
        s_xy[p] = make_float4(-2.0f * x0, -2.0f * x1, -2.0f * y0, -2.0f * y1);
        s_zw[p] = make_float4(-2.0f * z0, -2.0f * z1,
                              fmaf(x0, x0, fmaf(y0, y0, z0 * z0)),
                              fmaf(x1, x1, fmaf(y1, y1, z1 * z1)));
    }
    __syncthreads();

    // --- load queries, broadcast-pack into f32x2 operands
    const int q0 = blockIdx.x * QBLK;
    unsigned long long qx2[QPT], qy2[QPT], qz2[QPT];
    float q2[QPT], mn[QPT];
#pragma unroll
    for (int j = 0; j < QPT; j++) {
        int q = q0 + threadIdx.x + j * THREADS;
        float x = qbase[q * 3 + 0];
        float y = qbase[q * 3 + 1];
        float z = qbase[q * 3 + 2];
        asm("mov.b64 %0, {%1, %1};" : "=l"(qx2[j]) : "f"(x));
        asm("mov.b64 %0, {%1, %1};" : "=l"(qy2[j]) : "f"(y));
        asm("mov.b64 %0, {%1, %1};" : "=l"(qz2[j]) : "f"(z));
        q2[j] = fmaf(x, x, fmaf(y, y, z * z));
        mn[j] = CUDART_INF_F;
    }

    const ulonglong2* __restrict__ pXY = reinterpret_cast<const ulonglong2*>(s_xy);
    const ulonglong2* __restrict__ pZW = reinterpret_cast<const ulonglong2*>(s_zw);

    // --- main loop: per target-pair per query: 3 FFMA2 (fma pipe) + 2 FMNMX (alu)
#pragma unroll 8
    for (int p = 0; p < TTP; p++) {
        ulonglong2 xy = pXY[p];   // .x = (x0,x1), .y = (y0,y1)
        ulonglong2 zw = pZW[p];   // .x = (z0,z1), .y = (w0,w1)
#pragma unroll
        for (int j = 0; j < QPT; j++) {
            float s0, s1;
            asm("{\n\t"
                ".reg .b64 d;\n\t"
                "fma.rn.f32x2 d, %2, %3, %4;\n\t"
                "fma.rn.f32x2 d, %5, %6, d;\n\t"
                "fma.rn.f32x2 d, %7, %8, d;\n\t"
                "mov.b64 {%0, %1}, d;\n\t"
                "}"
                : "=f"(s0), "=f"(s1)
                : "l"(zw.x), "l"(qz2[j]), "l"(zw.y),
                  "l"(xy.y), "l"(qy2[j]),
                  "l"(xy.x), "l"(qx2[j]));
            mn[j] = fminf(fminf(mn[j], s0), s1);
        }
    }

    // --- plain-store partial mins (|q|^2 folded in here)
    float* part = g_partial + ((size_t)blockIdx.y * NDIRB + bz) * NPTS;
#pragma unroll
    for (int j = 0; j < QPT; j++) {
        int q = q0 + threadIdx.x + j * THREADS;
        part[q] = mn[j] + q2[j];
    }
}

// Single-block deterministic reduction:
// final[q] = min over tiles; loss = sum(final) / (B * N)
__global__ __launch_bounds__(1024)
void chamfer_reduce_kernel(float* __restrict__ out) {
    __shared__ float s_sum[1024];
    const float4* __restrict__ P = reinterpret_cast<const float4*>(g_partial);
    const int STRIDE4 = (NDIRB * NPTS) / 4;  // 8192 float4 slots per tile

    float acc = 0.0f;
    for (int s = threadIdx.x; s < STRIDE4; s += 1024) {
        float4 a = P[s];
        float4 b = P[STRIDE4 + s];
        float4 c = P[2 * STRIDE4 + s];
        float4 d = P[3 * STRIDE4 + s];
        float mx = fminf(fminf(a.x, b.x), fminf(c.x, d.x));
        float my = fminf(fminf(a.y, b.y), fminf(c.y, d.y));
        float mz = fminf(fminf(a.z, b.z), fminf(c.z, d.z));
        float mw = fminf(fminf(a.w, b.w), fminf(c.w, d.w));
        acc += (mx + my) + (mz + mw);
    }
    s_sum[threadIdx.x] = acc;
    __syncthreads();
    for (int stride = 512; stride > 0; stride >>= 1) {
        if (threadIdx.x < stride) s_sum[threadIdx.x] += s_sum[threadIdx.x + stride];
        __syncthreads();
    }
    if (threadIdx.x == 0)
        out[0] = s_sum[0] / (float)(BATCH * NPTS);
}

extern "C" void kernel_launch(void* const* d_in, const int* in_sizes, int n_in,
                              void* d_out, int out_size) {
    const float* src = (const float*)d_in[0];  // (B, N, 3)
    const float* tgt = (const float*)d_in[1];  // (B, M, 3)
    float* out = (float*)d_out;

    dim3 grid(NQBLK, NTTILE, NDIRB);  // 8 x 4 x 8 = 256 blocks
    chamfer_min_kernel<<<grid, THREADS>>>(src, tgt);

    chamfer_reduce_kernel<<<1, 1024>>>(out);
}